// round 2
// baseline (speedup 1.0000x reference)
#include <cuda_runtime.h>

#define NUM_CLASSES 1000
#define BATCH 8192
#define DD 4096   // dense dim

// ---- graph-safe scratch (no allocations allowed) ----
__device__ double g_loss1;                 // CE sum over rows
__device__ double g_loss2;                 // BCE sum over elements
__device__ int    g_offsets[NUM_CLASSES + 1];
__device__ int    g_cursor [NUM_CLASSES];
__device__ int    g_sorted [BATCH];

// ---------------------------------------------------------------------------
// K1: histogram of targets + prefix scan (single block). Also writes
// total_accumulated (= float counts) and zeroes the loss accumulators so the
// launch is deterministic across graph replays.
// ---------------------------------------------------------------------------
__global__ void hist_scan_kernel(const int* __restrict__ target,
                                 float* __restrict__ out_ta) {
    __shared__ int cnt[1024];
    __shared__ int s[1024];
    const int tid = threadIdx.x;
    cnt[tid] = 0;
    __syncthreads();
    for (int i = tid; i < BATCH; i += 1024)
        atomicAdd(&cnt[target[i]], 1);
    __syncthreads();

    const int myc = (tid < NUM_CLASSES) ? cnt[tid] : 0;
    if (tid < NUM_CLASSES) out_ta[tid] = (float)myc;

    // Hillis-Steele inclusive scan over 1024 slots (1000 valid)
    s[tid] = myc;
    __syncthreads();
    for (int off = 1; off < 1024; off <<= 1) {
        int t = (tid >= off) ? s[tid - off] : 0;
        __syncthreads();
        s[tid] += t;
        __syncthreads();
    }
    if (tid < NUM_CLASSES) {
        g_offsets[tid + 1] = s[tid];
        g_cursor[tid]      = s[tid] - myc;   // exclusive
    }
    if (tid == 0) {
        g_offsets[0] = 0;
        g_loss1 = 0.0;
        g_loss2 = 0.0;
    }
}

// ---------------------------------------------------------------------------
// K2: counting-sort scatter of batch indices by class.
// ---------------------------------------------------------------------------
__global__ void scatter_kernel(const int* __restrict__ target) {
    const int i = blockIdx.x * blockDim.x + threadIdx.x;
    if (i < BATCH) {
        const int t = target[i];
        const int p = atomicAdd(&g_cursor[t], 1);
        g_sorted[p] = i;
    }
}

// ---------------------------------------------------------------------------
// K3: fused segment-sum of sigmoid(dense_out) + BCE loss.
// grid = (4 column-chunks, 1000 classes), 256 threads, 1 float4 per thread.
// Each output element of dense_output_sum written exactly once (no atomics).
// ---------------------------------------------------------------------------
__device__ __forceinline__ void sig_bce(float x, float y, float& sig, float& bce) {
    const float ax  = fabsf(x);
    const float e   = __expf(-ax);                  // exp(-|x|)
    const float sp  = __fdividef(1.f, 1.f + e);     // sigmoid(|x|)
    sig = (x >= 0.f) ? sp : (1.f - sp);             // sigmoid(x)
    bce = fmaxf(x, 0.f) - x * y + __logf(1.f + e);  // stable BCE-with-logits
}

__global__ void dense_kernel(const float* __restrict__ dense_out,
                             const float* __restrict__ dense_labels,
                             float* __restrict__ out_ds) {
    const int c    = blockIdx.y;
    const int col4 = blockIdx.x * blockDim.x + threadIdx.x;  // 0..1023 (float4 idx)

    const float4 y = ((const float4*)(dense_labels + (size_t)c * DD))[col4];

    const int s = g_offsets[c];
    const int e = g_offsets[c + 1];

    float4 acc = make_float4(0.f, 0.f, 0.f, 0.f);
    float  lsum = 0.f;

    for (int i = s; i < e; ++i) {
        const int r = g_sorted[i];
        const float4 x = ((const float4*)(dense_out + (size_t)r * DD))[col4];
        float sg, bc;
        sig_bce(x.x, y.x, sg, bc); acc.x += sg; lsum += bc;
        sig_bce(x.y, y.y, sg, bc); acc.y += sg; lsum += bc;
        sig_bce(x.z, y.z, sg, bc); acc.z += sg; lsum += bc;
        sig_bce(x.w, y.w, sg, bc); acc.w += sg; lsum += bc;
    }

    // out_ds is offset by +1 float in d_out => only 4B-aligned: scalar stores.
    float* dst = out_ds + (size_t)c * DD + (size_t)col4 * 4;
    dst[0] = acc.x; dst[1] = acc.y; dst[2] = acc.z; dst[3] = acc.w;

    // block-reduce the BCE partial
    #pragma unroll
    for (int o = 16; o; o >>= 1)
        lsum += __shfl_xor_sync(0xffffffffu, lsum, o);
    __shared__ float wpart[8];
    const int wid = threadIdx.x >> 5, lane = threadIdx.x & 31;
    if (lane == 0) wpart[wid] = lsum;
    __syncthreads();
    if (threadIdx.x == 0) {
        float bs = 0.f;
        #pragma unroll
        for (int w = 0; w < 8; ++w) bs += wpart[w];
        atomicAdd(&g_loss2, (double)bs);
    }
}

// ---------------------------------------------------------------------------
// K4: cross-entropy over logits. One warp per row (1000 cols held in regs).
// ---------------------------------------------------------------------------
__global__ void ce_kernel(const float* __restrict__ logits,
                          const int* __restrict__ target) {
    const int warp = threadIdx.x >> 5;
    const int lane = threadIdx.x & 31;
    const int r    = blockIdx.x * 8 + warp;

    const float* row = logits + (size_t)r * NUM_CLASSES;

    float v[32];
    float m = -1e30f;
    #pragma unroll
    for (int k = 0; k < 32; ++k) {
        const int cc = k * 32 + lane;
        v[k] = (cc < NUM_CLASSES) ? row[cc] : -1e30f;
        m = fmaxf(m, v[k]);
    }
    #pragma unroll
    for (int o = 16; o; o >>= 1)
        m = fmaxf(m, __shfl_xor_sync(0xffffffffu, m, o));

    float ssum = 0.f;
    #pragma unroll
    for (int k = 0; k < 32; ++k)
        ssum += __expf(v[k] - m);   // padded lanes: expf(-huge) == 0
    #pragma unroll
    for (int o = 16; o; o >>= 1)
        ssum += __shfl_xor_sync(0xffffffffu, ssum, o);

    __shared__ float part[8];
    if (lane == 0)
        part[warp] = (__logf(ssum) + m) - row[target[r]];
    __syncthreads();
    if (threadIdx.x == 0) {
        float bs = 0.f;
        #pragma unroll
        for (int w = 0; w < 8; ++w) bs += part[w];
        atomicAdd(&g_loss1, (double)bs);
    }
}

// ---------------------------------------------------------------------------
// K5: combine losses into out[0].
// ---------------------------------------------------------------------------
__global__ void final_kernel(float* __restrict__ out) {
    const double l1 = g_loss1 / (double)BATCH;
    const double l2 = g_loss2 / ((double)BATCH * (double)DD);
    out[0] = (float)(0.5 * l1 + 0.5 * l2);
}

// ---------------------------------------------------------------------------
extern "C" void kernel_launch(void* const* d_in, const int* in_sizes, int n_in,
                              void* d_out, int out_size) {
    const float* logits       = (const float*)d_in[0];
    const float* dense_out    = (const float*)d_in[1];
    const int*   target       = (const int*)  d_in[2];
    const float* dense_labels = (const float*)d_in[3];

    float* out    = (float*)d_out;
    float* out_ds = out + 1;                               // dense_output_sum [1000,4096]
    float* out_ta = out + 1 + (size_t)NUM_CLASSES * DD;    // total_accumulated [1000]

    hist_scan_kernel<<<1, 1024>>>(target, out_ta);
    scatter_kernel<<<BATCH / 256, 256>>>(target);
    dense_kernel<<<dim3(4, NUM_CLASSES), 256>>>(dense_out, dense_labels, out_ds);
    ce_kernel<<<BATCH / 8, 256>>>(logits, target);
    final_kernel<<<1, 1>>>(out);
}